// round 17
// baseline (speedup 1.0000x reference)
#include <cuda_runtime.h>
#include <cuda_fp16.h>
#include <cstdint>

#define V    16     // output rows per thread (rolling 5-slot accumulator ring)
#define XPT  4      // output cols per thread (two half2 pairs)
#define RIN  (V + 4)
#define WIMG 1024
#define HIMG 1024

__constant__ __half2 c_w2[25];        // packed (w,w) per tap — constant loads, 0 GPRs
__device__   __half2 g_w2_stage[25];  // staging (device-writable scratch)

__global__ void prep_weights(const float* __restrict__ filt)
{
    const int t = threadIdx.x;
    if (t < 25) g_w2_stage[t] = __floats2half2_rn(filt[t], filt[t]);
}

// (hi(a), lo(b)) from two half2's: bytes {a.b2,a.b3,b.b0,b.b1}.
__device__ __forceinline__ __half2 shift_pair(__half2 a, __half2 b)
{
    const uint32_t r = __byte_perm(*reinterpret_cast<uint32_t*>(&a),
                                   *reinterpret_cast<uint32_t*>(&b), 0x5432);
    return *reinterpret_cast<const __half2*>(&r);
}

__global__ __launch_bounds__(256, 4)
void erosion5x5_kernel(const float* __restrict__ img,
                       float* __restrict__ out)
{
    const int plane = blockIdx.y;                 // fused (b,c): 0..95
    const int y0    = blockIdx.x * V;             // output row base
    const int x0    = threadIdx.x * XPT;          // 0, 4, ..., 1020

    const float* p = img + (size_t)plane * HIMG * WIMG;
    float*       q = out + (size_t)plane * HIMG * WIMG + (size_t)y0 * WIMG + x0;

    const float   INF  = __int_as_float(0x7f800000);
    const __half2 INF2 = __floats2half2_rn(INF, INF);

    // Thread needs cols x0-2 .. x0+5.
    const bool leftEdge  = (x0 == 0);
    const bool rightEdge = (x0 + 4 >= WIMG);      // only x0==1020

    // R12's proven row loader: all three loads under one branch, batched.
    auto load_row = [&](int r, float2& a, float4& b, float2& c2) {
        const int yy = y0 - 2 + r;
        if (yy >= 0 && yy < HIMG) {
            const float* row = p + (size_t)yy * WIMG + x0;
            a  = leftEdge  ? make_float2(INF, INF)
                           : *reinterpret_cast<const float2*>(row - 2);
            b  = *reinterpret_cast<const float4*>(row);
            c2 = rightEdge ? make_float2(INF, INF)
                           : *reinterpret_cast<const float2*>(row + 4);
        } else {
            a  = make_float2(INF, INF);
            b  = make_float4(INF, INF, INF, INF);
            c2 = make_float2(INF, INF);
        }
    };

    // Rolling accumulator ring: at input row r only outputs r-4..r are live.
    __half2 acc[5][2];
#pragma unroll
    for (int s = 0; s < 5; ++s) { acc[s][0] = INF2; acc[s][1] = INF2; }

    // Software pipeline (distance 1, R12 shape).
    float2 a_cur, c_cur;  float4 b_cur;
    load_row(0, a_cur, b_cur, c_cur);

#pragma unroll
    for (int r = 0; r < RIN; ++r) {
        float2 a_nxt, c_nxt;  float4 b_nxt;
        if (r + 1 < RIN) load_row(r + 1, a_nxt, b_nxt, c_nxt);

        // Pack current row: 4 cvt + 3 PRMT (bitwise = converting each pair).
        __half2 P[7];
        P[0] = __floats2half2_rn(a_cur.x, a_cur.y);   // (s0,s1)
        P[2] = __floats2half2_rn(b_cur.x, b_cur.y);   // (s2,s3)
        P[4] = __floats2half2_rn(b_cur.z, b_cur.w);   // (s4,s5)
        P[6] = __floats2half2_rn(c_cur.x, c_cur.y);   // (s6,s7)
        P[1] = shift_pair(P[0], P[2]);                // (s1,s2)
        P[3] = shift_pair(P[2], P[4]);                // (s3,s4)
        P[5] = shift_pair(P[4], P[6]);                // (s5,s6)

        // Input row r feeds output row o = r - i through filter row i.
#pragma unroll
        for (int i = 0; i < 5; ++i) {
            const int o = r - i;
            if (o < 0 || o >= V) continue;     // compile-time pruned
            const int s = o % 5;               // compile-time constant slot
#pragma unroll
            for (int j = 0; j < 5; ++j) {
                const __half2 w = c_w2[i * 5 + j];   // constant load, 0 GPRs
                acc[s][0] = __hmin2(acc[s][0], __hsub2(P[j],     w));   // cols (0,1)
                acc[s][1] = __hmin2(acc[s][1], __hsub2(P[j + 2], w));   // cols (2,3)
            }
        }

        // Output row r-4 is complete: store it, recycle its ring slot.
        if (r >= 4) {
            const int o = r - 4;               // 0..V-1, compile-time
            const int s = o % 5;
            const float2 lo = __half22float2(acc[s][0]);
            const float2 hi = __half22float2(acc[s][1]);
            float4 v = make_float4(lo.x, lo.y, hi.x, hi.y);
            *reinterpret_cast<float4*>(q + (size_t)o * WIMG) = v;   // STG.128
            acc[s][0] = INF2;  acc[s][1] = INF2;   // ready for output row o+5
        }

        a_cur = a_nxt;  b_cur = b_nxt;  c_cur = c_nxt;
    }
}

extern "C" void kernel_launch(void* const* d_in, const int* in_sizes, int n_in,
                              void* d_out, int out_size)
{
    const float* img  = (const float*)d_in[0];
    const float* filt = (const float*)d_in[1];
    float*       out  = (float*)d_out;

    // 1) Convert filter -> packed half2 in device staging array.
    prep_weights<<<1, 32>>>(filt);

    // 2) Stage -> constant bank (D2D memcpy node; graph-capturable, no alloc).
    void* stage_ptr = nullptr;
    cudaGetSymbolAddress(&stage_ptr, g_w2_stage);
    cudaMemcpyToSymbolAsync(c_w2, stage_ptr, 25 * sizeof(__half2), 0,
                            cudaMemcpyDeviceToDevice, 0);

    const int planes = in_sizes[0] / (HIMG * WIMG);   // 32*3 = 96

    dim3 block(WIMG / XPT);          // 256 threads: one row-strip of the plane
    dim3 grid(HIMG / V, planes);     // (64, 96)
    erosion5x5_kernel<<<grid, block>>>(img, out);
}